// round 15
// baseline (speedup 1.0000x reference)
#include <cuda_runtime.h>
#include <cuda_fp16.h>
#include <cstdint>

#define B_  8
#define N_  1024
#define C_  768
#define H_  12
#define D_  64
#define BH_ (B_*H_)     // 96
#define M_  (B_*N_)     // 8192
#define TC_ (3*C_)      // 2304

// Scratch (device globals: allocation-free rule)
__device__ __half g_Q  [(size_t)BH_ * N_ * D_]; // [B*H, N, D] norm*scale*log2e
__device__ __half g_K  [(size_t)BH_ * N_ * D_]; // [B*H, N, D] normalized
__device__ __half g_V  [(size_t)BH_ * N_ * D_]; // [B*H, N, D]
__device__ __half g_AO [(size_t)M_ * C_];       // [B*N, C] attn out fp16
__device__ __half g_Xh [(size_t)M_ * C_];       // x fp16
__device__ __half g_Wq [(size_t)TC_ * C_];      // qkv_w fp16
__device__ __half g_Wp [(size_t)C_ * C_];       // proj_w fp16

// ---------------------------------------------------------------------------
// helpers
// ---------------------------------------------------------------------------
__device__ __forceinline__ uint32_t smem_u32(const void* p) {
    uint32_t a;
    asm("{ .reg .u64 t; cvta.to.shared.u64 t, %1; cvt.u32.u64 %0, t; }" : "=r"(a) : "l"(p));
    return a;
}

__device__ __forceinline__ void cp_async16(uint32_t dst, const void* src) {
    asm volatile("cp.async.cg.shared.global [%0], [%1], 16;" :: "r"(dst), "l"(src) : "memory");
}
#define CP_COMMIT()   asm volatile("cp.async.commit_group;" ::: "memory")
#define CP_WAIT(n)    asm volatile("cp.async.wait_group %0;" :: "n"(n) : "memory")

#define LDSM4(R0,R1,R2,R3,ADDR) \
    asm volatile("ldmatrix.sync.aligned.m8n8.x4.shared.b16 {%0,%1,%2,%3}, [%4];" \
        : "=r"(R0),"=r"(R1),"=r"(R2),"=r"(R3) : "r"(ADDR))
#define LDSM4T(R0,R1,R2,R3,ADDR) \
    asm volatile("ldmatrix.sync.aligned.m8n8.x4.trans.shared.b16 {%0,%1,%2,%3}, [%4];" \
        : "=r"(R0),"=r"(R1),"=r"(R2),"=r"(R3) : "r"(ADDR))

// D(16x8) += A(16x16) * B(16x8), fp16 in, fp32 accum
__device__ __forceinline__ void mma_f16(float* d, const unsigned* a, const unsigned* b) {
    asm volatile("mma.sync.aligned.m16n8k16.row.col.f32.f16.f16.f32 "
                 "{%0,%1,%2,%3}, {%4,%5,%6,%7}, {%8,%9}, {%0,%1,%2,%3};"
                 : "+f"(d[0]), "+f"(d[1]), "+f"(d[2]), "+f"(d[3])
                 : "r"(a[0]), "r"(a[1]), "r"(a[2]), "r"(a[3]),
                   "r"(b[0]), "r"(b[1]));
}

__device__ __forceinline__ unsigned pack_h2(float lo, float hi) {
    __half2 h = __floats2half2_rn(lo, hi);
    return *reinterpret_cast<unsigned*>(&h);
}

__device__ __forceinline__ float ex2(float x) {
    float r; asm("ex2.approx.f32 %0, %1;" : "=f"(r) : "f"(x)); return r;
}

// ---------------------------------------------------------------------------
// fused fp32 -> fp16 conversion of all three operands (one launch)
// ---------------------------------------------------------------------------
#define CVT_N0 (M_ * C_)
#define CVT_N1 (TC_ * C_)
#define CVT_N2 (C_ * C_)

__global__ void __launch_bounds__(256) cvt_all_kernel(
    const float* __restrict__ x, const float* __restrict__ wqf,
    const float* __restrict__ wpf,
    __half* __restrict__ xh, __half* __restrict__ wq, __half* __restrict__ wp)
{
    int i = (blockIdx.x * 256 + threadIdx.x) * 4;
    const float* in; __half* out;
    if (i < CVT_N0)            { in = x;   out = xh; }
    else if (i < CVT_N0+CVT_N1){ i -= CVT_N0; in = wqf; out = wq; }
    else                       { i -= CVT_N0 + CVT_N1; in = wpf; out = wp; }
    const float4 v = *(const float4*)(in + i);
    uint2 u;
    u.x = pack_h2(v.x, v.y);
    u.y = pack_h2(v.z, v.w);
    *(uint2*)(out + i) = u;
}

// ---------------------------------------------------------------------------
// QKV GEMM (unchanged): CTA 256x128, BK=64, 3-stage ring, 8 warps,
// warp 64x64, register double-buffered fragments, multistage ordering.
// Fused q/k standardization; Q scale folds softmax scale AND log2(e).
// ---------------------------------------------------------------------------
#define GKS     72
#define GAB     (256 * GKS * 2)
#define GBB     (128 * GKS * 2)
#define GSTGB   (GAB + GBB)               // 55296
#define GSTG    3
#define GSMEMB  (GSTG * GSTGB)            // 165888

#define QSCALE  0.18033688f               // 0.125 * log2(e)

__global__ void __launch_bounds__(256, 1) gemm_qkv(
    const __half* __restrict__ A, const __half* __restrict__ W,
    __half* __restrict__ Qo, __half* __restrict__ Ko, __half* __restrict__ Vo,
    int K)
{
    extern __shared__ __half smh[];
    const uint32_t sbase = smem_u32(smh);

    const int tid = threadIdx.x;
    const int wid = tid >> 5, lane = tid & 31;
    const int lr = lane >> 2, lc = lane & 3;
    const int wm = (wid >> 1) * 64;
    const int wn = (wid & 1) * 64;
    const int m0 = blockIdx.y * 256, n0 = blockIdx.x * 128;
    const int KT = K >> 6;

    auto issue = [&](int s, int kt) {
        const uint32_t st = sbase + (uint32_t)s * GSTGB;
        #pragma unroll
        for (int j = 0; j < 12; ++j) {
            const int id = tid + j * 256;
            if (id < 2048) {
                const int r = id >> 3, c = id & 7;
                cp_async16(st + r * (GKS * 2) + c * 16,
                           A + (size_t)(m0 + r) * K + kt * 64 + c * 8);
            } else {
                const int idx = id - 2048;
                const int r = idx >> 3, c = idx & 7;
                cp_async16(st + GAB + r * (GKS * 2) + c * 16,
                           W + (size_t)(n0 + r) * K + kt * 64 + c * 8);
            }
        }
        CP_COMMIT();
    };

    auto ldA = [&](unsigned af[4][4], uint32_t Ab, int ks) {
        #pragma unroll
        for (int mt = 0; mt < 4; ++mt) {
            const uint32_t ad = Ab + (wm + mt * 16 + (lane & 15)) * (GKS * 2)
                              + ks * 32 + (lane >> 4) * 16;
            LDSM4(af[mt][0], af[mt][1], af[mt][2], af[mt][3], ad);
        }
    };
    auto ldB = [&](unsigned bf[8][2], uint32_t Bb, int ks) {
        #pragma unroll
        for (int ng = 0; ng < 4; ++ng) {
            const uint32_t bd = Bb + (wn + ng * 16 + ((lane >> 4) & 1) * 8 + (lane & 7)) * (GKS * 2)
                              + ks * 32 + ((lane >> 3) & 1) * 16;
            LDSM4(bf[2*ng][0], bf[2*ng][1], bf[2*ng+1][0], bf[2*ng+1][1], bd);
        }
    };

    float acc[4][8][4] = {};
    unsigned afb[2][4][4], bfb[2][8][2];

    auto hmma = [&](int p) {
        #pragma unroll
        for (int mt = 0; mt < 4; ++mt)
            #pragma unroll
            for (int nt = 0; nt < 8; ++nt)
                mma_f16(acc[mt][nt], afb[p][mt], bfb[p][nt]);
    };

    issue(0, 0); issue(1, 1);
    CP_WAIT(1);
    __syncthreads();
    ldA(afb[0], sbase, 0); ldB(bfb[0], sbase + GAB, 0);

    for (int kt = 0; kt < KT; ++kt) {
        const uint32_t Abc = sbase + (uint32_t)(kt % GSTG) * GSTGB;
        const uint32_t Bbc = Abc + GAB;
        const uint32_t Abn = sbase + (uint32_t)((kt + 1) % GSTG) * GSTGB;
        const uint32_t Bbn = Abn + GAB;

        ldA(afb[1], Abc, 1); ldB(bfb[1], Bbc, 1);
        hmma(0);
        ldA(afb[0], Abc, 2); ldB(bfb[0], Bbc, 2);
        hmma(1);
        ldA(afb[1], Abc, 3); ldB(bfb[1], Bbc, 3);
        hmma(0);

        if (kt + 2 < KT) issue((kt + 2) % GSTG, kt + 2);
        else CP_COMMIT();
        CP_WAIT(1);
        __syncthreads();
        if (kt + 1 < KT) {
            ldA(afb[0], Abn, 0); ldB(bfb[0], Bbn, 0);
        }
        hmma(1);
    }

    const int gc   = n0 + wn;
    const int type = gc < C_ ? 0 : (gc < 2 * C_ ? 1 : 2);
    const int head = (gc - type * C_) >> 6;
    __half* basep  = type == 0 ? Qo : (type == 1 ? Ko : Vo);
    #pragma unroll
    for (int mt = 0; mt < 4; ++mt)
        #pragma unroll
        for (int rh = 0; rh < 2; ++rh) {
            const int r = m0 + wm + mt * 16 + rh * 8 + lr;
            const int b = r >> 10, n = r & 1023;
            __half* dst = basep + ((size_t)(b * H_ + head) * N_ + n) * 64;
            if (type < 2) {
                float s = 0.f, ss = 0.f;
                #pragma unroll
                for (int nt = 0; nt < 8; ++nt) {
                    const float v0 = acc[mt][nt][2*rh], v1 = acc[mt][nt][2*rh+1];
                    s  += v0 + v1;
                    ss += v0 * v0 + v1 * v1;
                }
                s  += __shfl_xor_sync(0xffffffffu, s, 1);
                s  += __shfl_xor_sync(0xffffffffu, s, 2);
                ss += __shfl_xor_sync(0xffffffffu, ss, 1);
                ss += __shfl_xor_sync(0xffffffffu, ss, 2);
                const float mean = s * (1.0f / 64.0f);
                const float var  = (ss - 64.0f * mean * mean) * (1.0f / 63.0f);
                const float sc   = rsqrtf(var) * (type == 0 ? QSCALE : 1.0f);
                #pragma unroll
                for (int nt = 0; nt < 8; ++nt)
                    *(unsigned*)&dst[nt * 8 + 2 * lc] =
                        pack_h2((acc[mt][nt][2*rh]   - mean) * sc,
                                (acc[mt][nt][2*rh+1] - mean) * sc);
            } else {
                #pragma unroll
                for (int nt = 0; nt < 8; ++nt)
                    *(unsigned*)&dst[nt * 8 + 2 * lc] =
                        pack_h2(acc[mt][nt][2*rh], acc[mt][nt][2*rh+1]);
            }
        }
}

// ---------------------------------------------------------------------------
// proj GEMM: CTA tile 128x96 (better lane balance: 512 CTAs on 296 lanes ->
// makespan 1.5x vs 2x at 128x128). 128 threads (4 warps, 2m x 2n), warp tile
// 64x48, BK=32, 5-stage ring, register double-buffered fragments, 2 CTAs/SM.
// fp32 out + bias.
// ---------------------------------------------------------------------------
#define PKS     40
#define PAB     (128 * PKS * 2)           // A region = 10240 B
#define PBB     (96 * PKS * 2)            // B region = 7680 B
#define PSTGB   (PAB + PBB)               // 17920
#define PSTG    5
#define PSMEMB  (PSTG * PSTGB)            // 89600

__global__ void __launch_bounds__(128, 2) gemm_p(
    const __half* __restrict__ A, const __half* __restrict__ W,
    const float* __restrict__ bias, float* __restrict__ outF,
    int Nn, int K)
{
    extern __shared__ __half smh[];
    const uint32_t sbase = smem_u32(smh);

    const int tid = threadIdx.x;
    const int wid = tid >> 5, lane = tid & 31;
    const int lr = lane >> 2, lc = lane & 3;
    const int wm = (wid >> 1) * 64;
    const int wn = (wid & 1) * 48;
    const int m0 = blockIdx.y * 128, n0 = blockIdx.x * 96;
    const int KT = K >> 5;                // 24

    auto issue = [&](int s, int kt) {
        const uint32_t st = sbase + (uint32_t)s * PSTGB;
        #pragma unroll
        for (int j = 0; j < 7; ++j) {
            const int id = tid + j * 128;         // 0..895
            if (id < 512) {                        // A: 128 rows x 4 chunks
                const int r = id >> 2, c = id & 3;
                cp_async16(st + r * (PKS * 2) + c * 16,
                           A + (size_t)(m0 + r) * K + kt * 32 + c * 8);
            } else {                               // B: 96 rows x 4 chunks
                const int idx = id - 512;
                const int r = idx >> 2, c = idx & 3;
                cp_async16(st + PAB + r * (PKS * 2) + c * 16,
                           W + (size_t)(n0 + r) * K + kt * 32 + c * 8);
            }
        }
        CP_COMMIT();
    };

    auto ldA = [&](unsigned af[4][4], uint32_t Ab, int ks) {
        #pragma unroll
        for (int mt = 0; mt < 4; ++mt) {
            const uint32_t ad = Ab + (wm + mt * 16 + (lane & 15)) * (PKS * 2)
                              + ks * 32 + (lane >> 4) * 16;
            LDSM4(af[mt][0], af[mt][1], af[mt][2], af[mt][3], ad);
        }
    };
    auto ldB = [&](unsigned bf[6][2], uint32_t Bb, int ks) {
        #pragma unroll
        for (int ng = 0; ng < 3; ++ng) {
            const uint32_t bd = Bb + (wn + ng * 16 + ((lane >> 4) & 1) * 8 + (lane & 7)) * (PKS * 2)
                              + ks * 32 + ((lane >> 3) & 1) * 16;
            LDSM4(bf[2*ng][0], bf[2*ng][1], bf[2*ng+1][0], bf[2*ng+1][1], bd);
        }
    };

    float acc[4][6][4] = {};
    unsigned afb[2][4][4], bfb[2][6][2];

    auto hmma = [&](int p) {
        #pragma unroll
        for (int mt = 0; mt < 4; ++mt)
            #pragma unroll
            for (int nt = 0; nt < 6; ++nt)
                mma_f16(acc[mt][nt], afb[p][mt], bfb[p][nt]);
    };

    issue(0, 0); issue(1, 1); issue(2, 2); issue(3, 3);
    CP_WAIT(3);
    __syncthreads();
    ldA(afb[0], sbase, 0); ldB(bfb[0], sbase + PAB, 0);

    for (int kt = 0; kt < KT; ++kt) {
        const uint32_t Abc = sbase + (uint32_t)(kt % PSTG) * PSTGB;
        const uint32_t Bbc = Abc + PAB;
        const uint32_t Abn = sbase + (uint32_t)((kt + 1) % PSTG) * PSTGB;
        const uint32_t Bbn = Abn + PAB;

        ldA(afb[1], Abc, 1); ldB(bfb[1], Bbc, 1);
        hmma(0);

        if (kt + 4 < KT) issue((kt + 4) % PSTG, kt + 4);
        else CP_COMMIT();
        CP_WAIT(3);
        __syncthreads();
        if (kt + 1 < KT) {
            ldA(afb[0], Abn, 0); ldB(bfb[0], Bbn, 0);
        }
        hmma(1);
    }

    #pragma unroll
    for (int mt = 0; mt < 4; ++mt)
        #pragma unroll
        for (int nt = 0; nt < 6; ++nt) {
            const int r = m0 + wm + mt * 16 + lr;
            const int col = n0 + wn + nt * 8 + 2 * lc;
            const float bx = bias[col], by = bias[col + 1];
            float2 v0, v1;
            v0.x = acc[mt][nt][0] + bx; v0.y = acc[mt][nt][1] + by;
            v1.x = acc[mt][nt][2] + bx; v1.y = acc[mt][nt][3] + by;
            *(float2*)&outF[(size_t)r * Nn + col] = v0;
            *(float2*)&outF[(size_t)(r + 8) * Nn + col] = v1;
        }
}

// ---------------------------------------------------------------------------
// Flash attention, fp16 HMMA, NO-MAX softmax (unchanged from R14).
// |S| <= 7.875 by Cauchy-Schwarz => exp2 fits fp16; P = ex2(S') directly.
// CTA = 128 threads (4 warps), warp owns 32 q-rows, 3-stage KV ring.
// ---------------------------------------------------------------------------
#define AQS   72
#define AQB   (128 * AQS * 2)
#define AKB   (64 * AQS * 2)
#define AKVS  (2 * AKB)
#define ASMEMB (AQB + 3 * AKVS)          // 73728

__global__ void __launch_bounds__(128, 2) attn_h(__half* __restrict__ AO)
{
    extern __shared__ __half smh[];
    const uint32_t Qb = smem_u32(smh);

    const int tid  = threadIdx.x;
    const int wid  = tid >> 5, lane = tid & 31;
    const int lr   = lane >> 2, lc = lane & 3;
    const int bh   = blockIdx.y;
    const int n0   = blockIdx.x * 128;
    const int b = bh / H_, h = bh % H_;

    const __half* Qg = g_Q + ((size_t)bh * N_ + n0) * 64;
    const __half* Kg = g_K + (size_t)bh * N_ * 64;
    const __half* Vg = g_V + (size_t)bh * N_ * 64;

    #pragma unroll
    for (int j = 0; j < 8; ++j) {
        const int id = tid + j * 128;
        const int r = id >> 3, c = id & 7;
        cp_async16(Qb + r * (AQS * 2) + c * 16, Qg + r * 64 + c * 8);
    }
    CP_COMMIT();

    auto issueKV = [&](int s, int t) {
        const uint32_t Kbs = Qb + AQB + (uint32_t)s * AKVS;
        const uint32_t Vbs = Kbs + AKB;
        #pragma unroll
        for (int j = 0; j < 8; ++j) {
            const int id = tid + j * 128;
            const int arr = id >> 9;
            const int idx = id & 511;
            const int r = idx >> 3, c = idx & 7;
            const __half* g = (arr ? Vg : Kg) + (size_t)(t * 64 + r) * 64 + c * 8;
            cp_async16((arr ? Vbs : Kbs) + r * (AQS * 2) + c * 16, g);
        }
        CP_COMMIT();
    };
    issueKV(0, 0); issueKV(1, 1);

    unsigned qf[2][4][4];
    float o[2][8][4] = {};
    float lv[2][2] = {};

    int sr = 0, sw = 2;
    for (int t = 0; t < 16; ++t) {
        CP_WAIT(1);
        __syncthreads();
        if (t + 2 < 16) issueKV(sw, t + 2);
        else CP_COMMIT();
        if (++sw == 3) sw = 0;

        if (t == 0) {
            #pragma unroll
            for (int mt = 0; mt < 2; ++mt)
                #pragma unroll
                for (int ks = 0; ks < 4; ++ks) {
                    const uint32_t ad = Qb + (wid * 32 + mt * 16 + (lane & 15)) * (AQS * 2)
                                      + ks * 32 + (lane >> 4) * 16;
                    LDSM4(qf[mt][ks][0], qf[mt][ks][1], qf[mt][ks][2], qf[mt][ks][3], ad);
                }
        }

        const uint32_t Kbs = Qb + AQB + (uint32_t)sr * AKVS;
        const uint32_t Vbs = Kbs + AKB;
        if (++sr == 3) sr = 0;

        // S = Q @ Ktile^T  (32 q-rows x 64 keys per warp)
        float s[2][8][4] = {};
        #pragma unroll
        for (int ks = 0; ks < 4; ++ks) {
            unsigned bf[8][2];
            #pragma unroll
            for (int ng = 0; ng < 4; ++ng) {
                const uint32_t bd = Kbs + (ng * 16 + ((lane >> 4) & 1) * 8 + (lane & 7)) * (AQS * 2)
                                  + ks * 32 + ((lane >> 3) & 1) * 16;
                LDSM4(bf[2*ng][0], bf[2*ng][1], bf[2*ng+1][0], bf[2*ng+1][1], bd);
            }
            #pragma unroll
            for (int mt = 0; mt < 2; ++mt)
                #pragma unroll
                for (int nt = 0; nt < 8; ++nt)
                    mma_f16(s[mt][nt], qf[mt][ks], bf[nt]);
        }

        // P = exp2(S), accumulate row sums (no max, no rescale)
        #pragma unroll
        for (int mt = 0; mt < 2; ++mt) {
            float ps0 = 0.f, ps1 = 0.f;
            #pragma unroll
            for (int nt = 0; nt < 8; ++nt) {
                s[mt][nt][0] = ex2(s[mt][nt][0]);
                s[mt][nt][1] = ex2(s[mt][nt][1]);
                s[mt][nt][2] = ex2(s[mt][nt][2]);
                s[mt][nt][3] = ex2(s[mt][nt][3]);
                ps0 += s[mt][nt][0] + s[mt][nt][1];
                ps1 += s[mt][nt][2] + s[mt][nt][3];
            }
            ps0 += __shfl_xor_sync(0xffffffffu, ps0, 1);
            ps0 += __shfl_xor_sync(0xffffffffu, ps0, 2);
            ps1 += __shfl_xor_sync(0xffffffffu, ps1, 1);
            ps1 += __shfl_xor_sync(0xffffffffu, ps1, 2);
            lv[mt][0] += ps0;
            lv[mt][1] += ps1;
        }

        // O += P @ Vtile
        #pragma unroll
        for (int ks = 0; ks < 4; ++ks) {
            unsigned pa[2][4];
            #pragma unroll
            for (int mt = 0; mt < 2; ++mt) {
                pa[mt][0] = pack_h2(s[mt][2*ks][0],   s[mt][2*ks][1]);
                pa[mt][1] = pack_h2(s[mt][2*ks][2],   s[mt][2*ks][3]);
                pa[mt][2] = pack_h2(s[mt][2*ks+1][0], s[mt][2*ks+1][1]);
                pa[mt][3] = pack_h2(s[mt][2*ks+1][2], s[mt][2*ks+1][3]);
            }
            unsigned bf[8][2];
            #pragma unroll
            for (int dg = 0; dg < 4; ++dg) {
                const uint32_t vd = Vbs
                    + (ks * 16 + (lane & 7) + ((lane >> 3) & 1) * 8) * (AQS * 2)
                    + (dg * 16 + (lane >> 4) * 8) * 2;
                LDSM4T(bf[2*dg][0], bf[2*dg][1], bf[2*dg+1][0], bf[2*dg+1][1], vd);
            }
            #pragma unroll
            for (int mt = 0; mt < 2; ++mt)
                #pragma unroll
                for (int nt = 0; nt < 8; ++nt)
                    mma_f16(o[mt][nt], pa[mt], bf[nt]);
        }
    }

    #pragma unroll
    for (int mt = 0; mt < 2; ++mt) {
        const float il0 = 1.f / lv[mt][0], il1 = 1.f / lv[mt][1];
        const int r0 = b * N_ + n0 + wid * 32 + mt * 16 + lr;
        __half* dst = AO + (size_t)r0 * C_ + h * 64;
        #pragma unroll
        for (int nt = 0; nt < 8; ++nt) {
            const int col = nt * 8 + 2 * lc;
            *(unsigned*)&dst[col] = pack_h2(o[mt][nt][0] * il0, o[mt][nt][1] * il0);
            *(unsigned*)&dst[(size_t)8 * C_ + col] = pack_h2(o[mt][nt][2] * il1, o[mt][nt][3] * il1);
        }
    }
}

// ---------------------------------------------------------------------------
extern "C" void kernel_launch(void* const* d_in, const int* in_sizes, int n_in,
                              void* d_out, int out_size)
{
    const float* x      = (const float*)d_in[0];
    const float* qkv_w  = (const float*)d_in[1];
    const float* proj_w = (const float*)d_in[2];
    const float* proj_b = (const float*)d_in[3];
    float* out = (float*)d_out;

    __half *q, *k, *v, *ao, *xh, *wq, *wp;
    cudaGetSymbolAddress((void**)&q,   g_Q);
    cudaGetSymbolAddress((void**)&k,   g_K);
    cudaGetSymbolAddress((void**)&v,   g_V);
    cudaGetSymbolAddress((void**)&ao,  g_AO);
    cudaGetSymbolAddress((void**)&xh,  g_Xh);
    cudaGetSymbolAddress((void**)&wq,  g_Wq);
    cudaGetSymbolAddress((void**)&wp,  g_Wp);

    cudaFuncSetAttribute(gemm_qkv, cudaFuncAttributeMaxDynamicSharedMemorySize, GSMEMB);
    cudaFuncSetAttribute(gemm_p,   cudaFuncAttributeMaxDynamicSharedMemorySize, PSMEMB);
    cudaFuncSetAttribute(attn_h,   cudaFuncAttributeMaxDynamicSharedMemorySize, ASMEMB);

    // 0) fused fp32 -> fp16 operand conversion (one launch)
    cvt_all_kernel<<<(CVT_N0 + CVT_N1 + CVT_N2) / 1024, 256>>>(
        x, qkv_w, proj_w, xh, wq, wp);
    // 1) QKV projection + fused q/k standardization -> g_Q, g_K, g_V
    gemm_qkv<<<dim3(TC_ / 128, M_ / 256), 256, GSMEMB>>>(xh, wq, q, k, v, C_);
    // 2) fp16 flash attention (no-max softmax) -> fp16 AO
    attn_h<<<dim3(N_ / 128, BH_), 128, ASMEMB>>>(ao);
    // 3) output projection + bias -> fp32 (128x96 tiles for lane balance)
    gemm_p<<<dim3(C_ / 96, M_ / 128), 128, PSMEMB>>>(ao, wp, proj_b, out, C_, C_);
}

// round 17
// speedup vs baseline: 1.0128x; 1.0128x over previous
#include <cuda_runtime.h>
#include <cuda_fp16.h>
#include <cstdint>

#define B_  8
#define N_  1024
#define C_  768
#define H_  12
#define D_  64
#define BH_ (B_*H_)     // 96
#define M_  (B_*N_)     // 8192
#define TC_ (3*C_)      // 2304

// Scratch (device globals: allocation-free rule)
__device__ __half g_Q  [(size_t)BH_ * N_ * D_]; // [B*H, N, D] norm*scale*log2e
__device__ __half g_K  [(size_t)BH_ * N_ * D_]; // [B*H, N, D] normalized
__device__ __half g_V  [(size_t)BH_ * N_ * D_]; // [B*H, N, D]
__device__ __half g_AO [(size_t)M_ * C_];       // [B*N, C] attn out fp16
__device__ __half g_Xh [(size_t)M_ * C_];       // x fp16
__device__ __half g_Wq [(size_t)TC_ * C_];      // qkv_w fp16
__device__ __half g_Wp [(size_t)C_ * C_];       // proj_w fp16

// ---------------------------------------------------------------------------
// helpers
// ---------------------------------------------------------------------------
__device__ __forceinline__ uint32_t smem_u32(const void* p) {
    uint32_t a;
    asm("{ .reg .u64 t; cvta.to.shared.u64 t, %1; cvt.u32.u64 %0, t; }" : "=r"(a) : "l"(p));
    return a;
}

__device__ __forceinline__ void cp_async16(uint32_t dst, const void* src) {
    asm volatile("cp.async.cg.shared.global [%0], [%1], 16;" :: "r"(dst), "l"(src) : "memory");
}
#define CP_COMMIT()   asm volatile("cp.async.commit_group;" ::: "memory")
#define CP_WAIT(n)    asm volatile("cp.async.wait_group %0;" :: "n"(n) : "memory")

#define LDSM4(R0,R1,R2,R3,ADDR) \
    asm volatile("ldmatrix.sync.aligned.m8n8.x4.shared.b16 {%0,%1,%2,%3}, [%4];" \
        : "=r"(R0),"=r"(R1),"=r"(R2),"=r"(R3) : "r"(ADDR))
#define LDSM4T(R0,R1,R2,R3,ADDR) \
    asm volatile("ldmatrix.sync.aligned.m8n8.x4.trans.shared.b16 {%0,%1,%2,%3}, [%4];" \
        : "=r"(R0),"=r"(R1),"=r"(R2),"=r"(R3) : "r"(ADDR))

// D(16x8) += A(16x16) * B(16x8), fp16 in, fp32 accum
__device__ __forceinline__ void mma_f16(float* d, const unsigned* a, const unsigned* b) {
    asm volatile("mma.sync.aligned.m16n8k16.row.col.f32.f16.f16.f32 "
                 "{%0,%1,%2,%3}, {%4,%5,%6,%7}, {%8,%9}, {%0,%1,%2,%3};"
                 : "+f"(d[0]), "+f"(d[1]), "+f"(d[2]), "+f"(d[3])
                 : "r"(a[0]), "r"(a[1]), "r"(a[2]), "r"(a[3]),
                   "r"(b[0]), "r"(b[1]));
}

__device__ __forceinline__ unsigned pack_h2(float lo, float hi) {
    __half2 h = __floats2half2_rn(lo, hi);
    return *reinterpret_cast<unsigned*>(&h);
}

__device__ __forceinline__ float ex2(float x) {
    float r; asm("ex2.approx.f32 %0, %1;" : "=f"(r) : "f"(x)); return r;
}

// ---------------------------------------------------------------------------
// fused fp32 -> fp16 conversion of all three operands (one launch)
// ---------------------------------------------------------------------------
#define CVT_N0 (M_ * C_)
#define CVT_N1 (TC_ * C_)
#define CVT_N2 (C_ * C_)

__global__ void __launch_bounds__(256) cvt_all_kernel(
    const float* __restrict__ x, const float* __restrict__ wqf,
    const float* __restrict__ wpf,
    __half* __restrict__ xh, __half* __restrict__ wq, __half* __restrict__ wp)
{
    int i = (blockIdx.x * 256 + threadIdx.x) * 4;
    const float* in; __half* out;
    if (i < CVT_N0)            { in = x;   out = xh; }
    else if (i < CVT_N0+CVT_N1){ i -= CVT_N0; in = wqf; out = wq; }
    else                       { i -= CVT_N0 + CVT_N1; in = wpf; out = wp; }
    const float4 v = *(const float4*)(in + i);
    uint2 u;
    u.x = pack_h2(v.x, v.y);
    u.y = pack_h2(v.z, v.w);
    *(uint2*)(out + i) = u;
}

// ---------------------------------------------------------------------------
// QKV GEMM (unchanged R14): CTA 256x128, BK=64, 3-stage ring, 8 warps,
// warp 64x64, register double-buffered fragments, multistage ordering.
// Fused q/k standardization; Q scale folds softmax scale AND log2(e).
// ---------------------------------------------------------------------------
#define GKS     72
#define GAB     (256 * GKS * 2)
#define GBB     (128 * GKS * 2)
#define GSTGB   (GAB + GBB)               // 55296
#define GSTG    3
#define GSMEMB  (GSTG * GSTGB)            // 165888

#define QSCALE  0.18033688f               // 0.125 * log2(e)

__global__ void __launch_bounds__(256, 1) gemm_qkv(
    const __half* __restrict__ A, const __half* __restrict__ W,
    __half* __restrict__ Qo, __half* __restrict__ Ko, __half* __restrict__ Vo,
    int K)
{
    extern __shared__ __half smh[];
    const uint32_t sbase = smem_u32(smh);

    const int tid = threadIdx.x;
    const int wid = tid >> 5, lane = tid & 31;
    const int lr = lane >> 2, lc = lane & 3;
    const int wm = (wid >> 1) * 64;
    const int wn = (wid & 1) * 64;
    const int m0 = blockIdx.y * 256, n0 = blockIdx.x * 128;
    const int KT = K >> 6;

    auto issue = [&](int s, int kt) {
        const uint32_t st = sbase + (uint32_t)s * GSTGB;
        #pragma unroll
        for (int j = 0; j < 12; ++j) {
            const int id = tid + j * 256;
            if (id < 2048) {
                const int r = id >> 3, c = id & 7;
                cp_async16(st + r * (GKS * 2) + c * 16,
                           A + (size_t)(m0 + r) * K + kt * 64 + c * 8);
            } else {
                const int idx = id - 2048;
                const int r = idx >> 3, c = idx & 7;
                cp_async16(st + GAB + r * (GKS * 2) + c * 16,
                           W + (size_t)(n0 + r) * K + kt * 64 + c * 8);
            }
        }
        CP_COMMIT();
    };

    auto ldA = [&](unsigned af[4][4], uint32_t Ab, int ks) {
        #pragma unroll
        for (int mt = 0; mt < 4; ++mt) {
            const uint32_t ad = Ab + (wm + mt * 16 + (lane & 15)) * (GKS * 2)
                              + ks * 32 + (lane >> 4) * 16;
            LDSM4(af[mt][0], af[mt][1], af[mt][2], af[mt][3], ad);
        }
    };
    auto ldB = [&](unsigned bf[8][2], uint32_t Bb, int ks) {
        #pragma unroll
        for (int ng = 0; ng < 4; ++ng) {
            const uint32_t bd = Bb + (wn + ng * 16 + ((lane >> 4) & 1) * 8 + (lane & 7)) * (GKS * 2)
                              + ks * 32 + ((lane >> 3) & 1) * 16;
            LDSM4(bf[2*ng][0], bf[2*ng][1], bf[2*ng+1][0], bf[2*ng+1][1], bd);
        }
    };

    float acc[4][8][4] = {};
    unsigned afb[2][4][4], bfb[2][8][2];

    auto hmma = [&](int p) {
        #pragma unroll
        for (int mt = 0; mt < 4; ++mt)
            #pragma unroll
            for (int nt = 0; nt < 8; ++nt)
                mma_f16(acc[mt][nt], afb[p][mt], bfb[p][nt]);
    };

    issue(0, 0); issue(1, 1);
    CP_WAIT(1);
    __syncthreads();
    ldA(afb[0], sbase, 0); ldB(bfb[0], sbase + GAB, 0);

    for (int kt = 0; kt < KT; ++kt) {
        const uint32_t Abc = sbase + (uint32_t)(kt % GSTG) * GSTGB;
        const uint32_t Bbc = Abc + GAB;
        const uint32_t Abn = sbase + (uint32_t)((kt + 1) % GSTG) * GSTGB;
        const uint32_t Bbn = Abn + GAB;

        ldA(afb[1], Abc, 1); ldB(bfb[1], Bbc, 1);
        hmma(0);
        ldA(afb[0], Abc, 2); ldB(bfb[0], Bbc, 2);
        hmma(1);
        ldA(afb[1], Abc, 3); ldB(bfb[1], Bbc, 3);
        hmma(0);

        if (kt + 2 < KT) issue((kt + 2) % GSTG, kt + 2);
        else CP_COMMIT();
        CP_WAIT(1);
        __syncthreads();
        if (kt + 1 < KT) {
            ldA(afb[0], Abn, 0); ldB(bfb[0], Bbn, 0);
        }
        hmma(1);
    }

    const int gc   = n0 + wn;
    const int type = gc < C_ ? 0 : (gc < 2 * C_ ? 1 : 2);
    const int head = (gc - type * C_) >> 6;
    __half* basep  = type == 0 ? Qo : (type == 1 ? Ko : Vo);
    #pragma unroll
    for (int mt = 0; mt < 4; ++mt)
        #pragma unroll
        for (int rh = 0; rh < 2; ++rh) {
            const int r = m0 + wm + mt * 16 + rh * 8 + lr;
            const int b = r >> 10, n = r & 1023;
            __half* dst = basep + ((size_t)(b * H_ + head) * N_ + n) * 64;
            if (type < 2) {
                float s = 0.f, ss = 0.f;
                #pragma unroll
                for (int nt = 0; nt < 8; ++nt) {
                    const float v0 = acc[mt][nt][2*rh], v1 = acc[mt][nt][2*rh+1];
                    s  += v0 + v1;
                    ss += v0 * v0 + v1 * v1;
                }
                s  += __shfl_xor_sync(0xffffffffu, s, 1);
                s  += __shfl_xor_sync(0xffffffffu, s, 2);
                ss += __shfl_xor_sync(0xffffffffu, ss, 1);
                ss += __shfl_xor_sync(0xffffffffu, ss, 2);
                const float mean = s * (1.0f / 64.0f);
                const float var  = (ss - 64.0f * mean * mean) * (1.0f / 63.0f);
                const float sc   = rsqrtf(var) * (type == 0 ? QSCALE : 1.0f);
                #pragma unroll
                for (int nt = 0; nt < 8; ++nt)
                    *(unsigned*)&dst[nt * 8 + 2 * lc] =
                        pack_h2((acc[mt][nt][2*rh]   - mean) * sc,
                                (acc[mt][nt][2*rh+1] - mean) * sc);
            } else {
                #pragma unroll
                for (int nt = 0; nt < 8; ++nt)
                    *(unsigned*)&dst[nt * 8 + 2 * lc] =
                        pack_h2(acc[mt][nt][2*rh], acc[mt][nt][2*rh+1]);
            }
        }
}

// ---------------------------------------------------------------------------
// proj GEMM: half-M clone of the QKV mainloop. CTA 128x128, 128 threads
// (4 warps, 2m x 2n, warp 64x64), BK=64 (KT=12 -> 128 MMAs per sync window),
// 3-stage ring, register double-buffered fragments, 2 CTAs/SM.
// fp32 out + bias.
// ---------------------------------------------------------------------------
#define PKS     72
#define PAB     (128 * PKS * 2)           // A region = 18432 B
#define PSTGB   (2 * PAB)                 // 36864
#define PSTG    3
#define PSMEMB  (PSTG * PSTGB)            // 110592

__global__ void __launch_bounds__(128, 2) gemm_p(
    const __half* __restrict__ A, const __half* __restrict__ W,
    const float* __restrict__ bias, float* __restrict__ outF,
    int Nn, int K)
{
    extern __shared__ __half smh[];
    const uint32_t sbase = smem_u32(smh);

    const int tid = threadIdx.x;
    const int wid = tid >> 5, lane = tid & 31;
    const int lr = lane >> 2, lc = lane & 3;
    const int wm = (wid >> 1) * 64;
    const int wn = (wid & 1) * 64;
    const int m0 = blockIdx.y * 128, n0 = blockIdx.x * 128;
    const int KT = K >> 6;                // 12

    auto issue = [&](int s, int kt) {
        const uint32_t st = sbase + (uint32_t)s * PSTGB;
        #pragma unroll
        for (int j = 0; j < 16; ++j) {
            const int id = tid + j * 128;          // 0..2047
            const int arr = id >> 10;              // 0=A, 1=B
            const int idx = id & 1023;
            const int r = idx >> 3, c = idx & 7;   // 128 rows x 8 chunks
            const __half* g = (arr ? W + (size_t)(n0 + r) * K
                                   : A + (size_t)(m0 + r) * K) + kt * 64 + c * 8;
            cp_async16(st + (uint32_t)arr * PAB + r * (PKS * 2) + c * 16, g);
        }
        CP_COMMIT();
    };

    auto ldA = [&](unsigned af[4][4], uint32_t Ab, int ks) {
        #pragma unroll
        for (int mt = 0; mt < 4; ++mt) {
            const uint32_t ad = Ab + (wm + mt * 16 + (lane & 15)) * (PKS * 2)
                              + ks * 32 + (lane >> 4) * 16;
            LDSM4(af[mt][0], af[mt][1], af[mt][2], af[mt][3], ad);
        }
    };
    auto ldB = [&](unsigned bf[8][2], uint32_t Bb, int ks) {
        #pragma unroll
        for (int ng = 0; ng < 4; ++ng) {
            const uint32_t bd = Bb + (wn + ng * 16 + ((lane >> 4) & 1) * 8 + (lane & 7)) * (PKS * 2)
                              + ks * 32 + ((lane >> 3) & 1) * 16;
            LDSM4(bf[2*ng][0], bf[2*ng][1], bf[2*ng+1][0], bf[2*ng+1][1], bd);
        }
    };

    float acc[4][8][4] = {};
    unsigned afb[2][4][4], bfb[2][8][2];

    auto hmma = [&](int p) {
        #pragma unroll
        for (int mt = 0; mt < 4; ++mt)
            #pragma unroll
            for (int nt = 0; nt < 8; ++nt)
                mma_f16(acc[mt][nt], afb[p][mt], bfb[p][nt]);
    };

    issue(0, 0); issue(1, 1);
    CP_WAIT(1);
    __syncthreads();
    ldA(afb[0], sbase, 0); ldB(bfb[0], sbase + PAB, 0);

    for (int kt = 0; kt < KT; ++kt) {
        const uint32_t Abc = sbase + (uint32_t)(kt % PSTG) * PSTGB;
        const uint32_t Bbc = Abc + PAB;
        const uint32_t Abn = sbase + (uint32_t)((kt + 1) % PSTG) * PSTGB;
        const uint32_t Bbn = Abn + PAB;

        ldA(afb[1], Abc, 1); ldB(bfb[1], Bbc, 1);
        hmma(0);
        ldA(afb[0], Abc, 2); ldB(bfb[0], Bbc, 2);
        hmma(1);
        ldA(afb[1], Abc, 3); ldB(bfb[1], Bbc, 3);
        hmma(0);

        if (kt + 2 < KT) issue((kt + 2) % PSTG, kt + 2);
        else CP_COMMIT();
        CP_WAIT(1);
        __syncthreads();
        if (kt + 1 < KT) {
            ldA(afb[0], Abn, 0); ldB(bfb[0], Bbn, 0);
        }
        hmma(1);
    }

    #pragma unroll
    for (int mt = 0; mt < 4; ++mt)
        #pragma unroll
        for (int nt = 0; nt < 8; ++nt) {
            const int r = m0 + wm + mt * 16 + lr;
            const int col = n0 + wn + nt * 8 + 2 * lc;
            const float bx = bias[col], by = bias[col + 1];
            float2 v0, v1;
            v0.x = acc[mt][nt][0] + bx; v0.y = acc[mt][nt][1] + by;
            v1.x = acc[mt][nt][2] + bx; v1.y = acc[mt][nt][3] + by;
            *(float2*)&outF[(size_t)r * Nn + col] = v0;
            *(float2*)&outF[(size_t)(r + 8) * Nn + col] = v1;
        }
}

// ---------------------------------------------------------------------------
// Flash attention, fp16 HMMA, NO-MAX softmax (unchanged from R14).
// |S| <= 7.875 by Cauchy-Schwarz => exp2 fits fp16; P = ex2(S') directly.
// CTA = 128 threads (4 warps), warp owns 32 q-rows, 3-stage KV ring.
// ---------------------------------------------------------------------------
#define AQS   72
#define AQB   (128 * AQS * 2)
#define AKB   (64 * AQS * 2)
#define AKVS  (2 * AKB)
#define ASMEMB (AQB + 3 * AKVS)          // 73728

__global__ void __launch_bounds__(128, 2) attn_h(__half* __restrict__ AO)
{
    extern __shared__ __half smh[];
    const uint32_t Qb = smem_u32(smh);

    const int tid  = threadIdx.x;
    const int wid  = tid >> 5, lane = tid & 31;
    const int lr   = lane >> 2, lc = lane & 3;
    const int bh   = blockIdx.y;
    const int n0   = blockIdx.x * 128;
    const int b = bh / H_, h = bh % H_;

    const __half* Qg = g_Q + ((size_t)bh * N_ + n0) * 64;
    const __half* Kg = g_K + (size_t)bh * N_ * 64;
    const __half* Vg = g_V + (size_t)bh * N_ * 64;

    #pragma unroll
    for (int j = 0; j < 8; ++j) {
        const int id = tid + j * 128;
        const int r = id >> 3, c = id & 7;
        cp_async16(Qb + r * (AQS * 2) + c * 16, Qg + r * 64 + c * 8);
    }
    CP_COMMIT();

    auto issueKV = [&](int s, int t) {
        const uint32_t Kbs = Qb + AQB + (uint32_t)s * AKVS;
        const uint32_t Vbs = Kbs + AKB;
        #pragma unroll
        for (int j = 0; j < 8; ++j) {
            const int id = tid + j * 128;
            const int arr = id >> 9;
            const int idx = id & 511;
            const int r = idx >> 3, c = idx & 7;
            const __half* g = (arr ? Vg : Kg) + (size_t)(t * 64 + r) * 64 + c * 8;
            cp_async16((arr ? Vbs : Kbs) + r * (AQS * 2) + c * 16, g);
        }
        CP_COMMIT();
    };
    issueKV(0, 0); issueKV(1, 1);

    unsigned qf[2][4][4];
    float o[2][8][4] = {};
    float lv[2][2] = {};

    int sr = 0, sw = 2;
    for (int t = 0; t < 16; ++t) {
        CP_WAIT(1);
        __syncthreads();
        if (t + 2 < 16) issueKV(sw, t + 2);
        else CP_COMMIT();
        if (++sw == 3) sw = 0;

        if (t == 0) {
            #pragma unroll
            for (int mt = 0; mt < 2; ++mt)
                #pragma unroll
                for (int ks = 0; ks < 4; ++ks) {
                    const uint32_t ad = Qb + (wid * 32 + mt * 16 + (lane & 15)) * (AQS * 2)
                                      + ks * 32 + (lane >> 4) * 16;
                    LDSM4(qf[mt][ks][0], qf[mt][ks][1], qf[mt][ks][2], qf[mt][ks][3], ad);
                }
        }

        const uint32_t Kbs = Qb + AQB + (uint32_t)sr * AKVS;
        const uint32_t Vbs = Kbs + AKB;
        if (++sr == 3) sr = 0;

        // S = Q @ Ktile^T  (32 q-rows x 64 keys per warp)
        float s[2][8][4] = {};
        #pragma unroll
        for (int ks = 0; ks < 4; ++ks) {
            unsigned bf[8][2];
            #pragma unroll
            for (int ng = 0; ng < 4; ++ng) {
                const uint32_t bd = Kbs + (ng * 16 + ((lane >> 4) & 1) * 8 + (lane & 7)) * (AQS * 2)
                                  + ks * 32 + ((lane >> 3) & 1) * 16;
                LDSM4(bf[2*ng][0], bf[2*ng][1], bf[2*ng+1][0], bf[2*ng+1][1], bd);
            }
            #pragma unroll
            for (int mt = 0; mt < 2; ++mt)
                #pragma unroll
                for (int nt = 0; nt < 8; ++nt)
                    mma_f16(s[mt][nt], qf[mt][ks], bf[nt]);
        }

        // P = exp2(S), accumulate row sums (no max, no rescale)
        #pragma unroll
        for (int mt = 0; mt < 2; ++mt) {
            float ps0 = 0.f, ps1 = 0.f;
            #pragma unroll
            for (int nt = 0; nt < 8; ++nt) {
                s[mt][nt][0] = ex2(s[mt][nt][0]);
                s[mt][nt][1] = ex2(s[mt][nt][1]);
                s[mt][nt][2] = ex2(s[mt][nt][2]);
                s[mt][nt][3] = ex2(s[mt][nt][3]);
                ps0 += s[mt][nt][0] + s[mt][nt][1];
                ps1 += s[mt][nt][2] + s[mt][nt][3];
            }
            ps0 += __shfl_xor_sync(0xffffffffu, ps0, 1);
            ps0 += __shfl_xor_sync(0xffffffffu, ps0, 2);
            ps1 += __shfl_xor_sync(0xffffffffu, ps1, 1);
            ps1 += __shfl_xor_sync(0xffffffffu, ps1, 2);
            lv[mt][0] += ps0;
            lv[mt][1] += ps1;
        }

        // O += P @ Vtile
        #pragma unroll
        for (int ks = 0; ks < 4; ++ks) {
            unsigned pa[2][4];
            #pragma unroll
            for (int mt = 0; mt < 2; ++mt) {
                pa[mt][0] = pack_h2(s[mt][2*ks][0],   s[mt][2*ks][1]);
                pa[mt][1] = pack_h2(s[mt][2*ks][2],   s[mt][2*ks][3]);
                pa[mt][2] = pack_h2(s[mt][2*ks+1][0], s[mt][2*ks+1][1]);
                pa[mt][3] = pack_h2(s[mt][2*ks+1][2], s[mt][2*ks+1][3]);
            }
            unsigned bf[8][2];
            #pragma unroll
            for (int dg = 0; dg < 4; ++dg) {
                const uint32_t vd = Vbs
                    + (ks * 16 + (lane & 7) + ((lane >> 3) & 1) * 8) * (AQS * 2)
                    + (dg * 16 + (lane >> 4) * 8) * 2;
                LDSM4T(bf[2*dg][0], bf[2*dg][1], bf[2*dg+1][0], bf[2*dg+1][1], vd);
            }
            #pragma unroll
            for (int mt = 0; mt < 2; ++mt)
                #pragma unroll
                for (int nt = 0; nt < 8; ++nt)
                    mma_f16(o[mt][nt], pa[mt], bf[nt]);
        }
    }

    #pragma unroll
    for (int mt = 0; mt < 2; ++mt) {
        const float il0 = 1.f / lv[mt][0], il1 = 1.f / lv[mt][1];
        const int r0 = b * N_ + n0 + wid * 32 + mt * 16 + lr;
        __half* dst = AO + (size_t)r0 * C_ + h * 64;
        #pragma unroll
        for (int nt = 0; nt < 8; ++nt) {
            const int col = nt * 8 + 2 * lc;
            *(unsigned*)&dst[col] = pack_h2(o[mt][nt][0] * il0, o[mt][nt][1] * il0);
            *(unsigned*)&dst[(size_t)8 * C_ + col] = pack_h2(o[mt][nt][2] * il1, o[mt][nt][3] * il1);
        }
    }
}

// ---------------------------------------------------------------------------
extern "C" void kernel_launch(void* const* d_in, const int* in_sizes, int n_in,
                              void* d_out, int out_size)
{
    const float* x      = (const float*)d_in[0];
    const float* qkv_w  = (const float*)d_in[1];
    const float* proj_w = (const float*)d_in[2];
    const float* proj_b = (const float*)d_in[3];
    float* out = (float*)d_out;

    __half *q, *k, *v, *ao, *xh, *wq, *wp;
    cudaGetSymbolAddress((void**)&q,   g_Q);
    cudaGetSymbolAddress((void**)&k,   g_K);
    cudaGetSymbolAddress((void**)&v,   g_V);
    cudaGetSymbolAddress((void**)&ao,  g_AO);
    cudaGetSymbolAddress((void**)&xh,  g_Xh);
    cudaGetSymbolAddress((void**)&wq,  g_Wq);
    cudaGetSymbolAddress((void**)&wp,  g_Wp);

    cudaFuncSetAttribute(gemm_qkv, cudaFuncAttributeMaxDynamicSharedMemorySize, GSMEMB);
    cudaFuncSetAttribute(gemm_p,   cudaFuncAttributeMaxDynamicSharedMemorySize, PSMEMB);
    cudaFuncSetAttribute(attn_h,   cudaFuncAttributeMaxDynamicSharedMemorySize, ASMEMB);

    // 0) fused fp32 -> fp16 operand conversion (one launch)
    cvt_all_kernel<<<(CVT_N0 + CVT_N1 + CVT_N2) / 1024, 256>>>(
        x, qkv_w, proj_w, xh, wq, wp);
    // 1) QKV projection + fused q/k standardization -> g_Q, g_K, g_V
    gemm_qkv<<<dim3(TC_ / 128, M_ / 256), 256, GSMEMB>>>(xh, wq, q, k, v, C_);
    // 2) fp16 flash attention (no-max softmax) -> fp16 AO
    attn_h<<<dim3(N_ / 128, BH_), 128, ASMEMB>>>(ao);
    // 3) output projection + bias -> fp32 (BK=64 mainloop, QKV clone)
    gemm_p<<<dim3(C_ / 128, M_ / 128), 128, PSMEMB>>>(ao, wp, proj_b, out, C_, C_);
}